// round 6
// baseline (speedup 1.0000x reference)
#include <cuda_runtime.h>
#include <cuda_fp16.h>
#include <stdint.h>

#define PN0 8192
#define PN1 16384
#define PN2 8192
#define PD  128
#define NTOT (PN0 + PN1 + PN2)
#define OFF1 ((long)PN0 * PD)
#define OFF2 ((long)(PN0 + PN1) * PD)

#define NUM_TILES 256   // 128 heavy (branch1) + 64 (branch0) + 64 (branch2)
#define GRID 152
#define SMEM_BASE 1024
#define STAGE_BYTES 49152          // A 16K | B_hi 16K | B_lo 16K
#define DYN_SMEM (SMEM_BASE + 2 * STAGE_BYTES)

// x^T hi/lo in fp16: g_bt_*[off + j*N + k] ~ x[k][j]  (hi + lo covers ~21 bits)
__device__ __half g_bt_hi[(long)NTOT * PD];
__device__ __half g_bt_lo[(long)NTOT * PD];
__device__ __half g_w16[3 * PD * PD];
__device__ unsigned g_ctr;

#define SWZ128(o) ((uint32_t)(o) ^ ((((uint32_t)(o)) >> 3) & 0x70))

__device__ __forceinline__ uint32_t smem_to_u32(const void* p) {
    uint32_t a;
    asm("{ .reg .u64 t; cvta.to.shared.u64 t, %1; cvt.u32.u64 %0, t; }" : "=r"(a) : "l"(p));
    return a;
}
__device__ __forceinline__ void ldsm_x4(uint32_t* r, uint32_t addr) {
    asm volatile("ldmatrix.sync.aligned.m8n8.x4.shared.b16 {%0,%1,%2,%3}, [%4];"
                 : "=r"(r[0]), "=r"(r[1]), "=r"(r[2]), "=r"(r[3]) : "r"(addr));
}
__device__ __forceinline__ void mma16816(float* c, const uint32_t* a, const uint32_t* b) {
    asm volatile("mma.sync.aligned.m16n8k16.row.col.f32.f16.f16.f32 "
                 "{%0,%1,%2,%3}, {%4,%5,%6,%7}, {%8,%9}, {%0,%1,%2,%3};"
                 : "+f"(c[0]), "+f"(c[1]), "+f"(c[2]), "+f"(c[3])
                 : "r"(a[0]), "r"(a[1]), "r"(a[2]), "r"(a[3]), "r"(b[0]), "r"(b[1]));
}
__device__ __forceinline__ uint32_t pack_h2(__half a, __half b) {
    __half2 t = __halves2half2(a, b);
    return *reinterpret_cast<uint32_t*>(&t);
}
__device__ __forceinline__ uint32_t cvt2(float x, float y) {
    __half2 t = __float22half2_rn(make_float2(x, y));   // single F2FP.PACK
    return *reinterpret_cast<uint32_t*>(&t);
}
#define CP_ASYNC16(dst, src) \
    asm volatile("cp.async.cg.shared.global [%0], [%1], 16;" :: "r"(dst), "l"(src))
#define CP_COMMIT() asm volatile("cp.async.commit_group;" ::: "memory")
#define CP_WAIT0()  asm volatile("cp.async.wait_group 0;" ::: "memory")

// acc += A * (B_hi + B_lo):  A single fp16 (split-free), B split hi/lo.
// sA: [128 m][64 k], sBh/sBl: [128 n][64 k], 128B rows, SW128.
__device__ __forceinline__ void mma_block_bsplit(float acc[2][8][4],
                                                 uint32_t sA, uint32_t sBh, uint32_t sBl,
                                                 int mrow, int ncol, int l) {
    const uint32_t a_lane = (uint32_t)((l & 15) * 128 + (l >> 4) * 16);
    const uint32_t b_lane = (uint32_t)(((l & 7) + ((l >> 4) & 1) * 8) * 128 + ((l >> 3) & 1) * 16);
    #pragma unroll
    for (int kb = 0; kb < 4; kb++) {
        uint32_t af[2][4], bh[4][4], bl[4][4];
        #pragma unroll
        for (int mi = 0; mi < 2; mi++) {
            uint32_t off = (uint32_t)((mrow + mi * 16) * 128 + kb * 32) + a_lane;
            ldsm_x4(af[mi], sA + SWZ128(off));
        }
        #pragma unroll
        for (int g = 0; g < 4; g++) {
            uint32_t off = (uint32_t)((ncol + g * 16) * 128 + kb * 32) + b_lane;
            ldsm_x4(bh[g], sBh + SWZ128(off));
            ldsm_x4(bl[g], sBl + SWZ128(off));
        }
        #pragma unroll
        for (int mi = 0; mi < 2; mi++)
            #pragma unroll
            for (int nb = 0; nb < 8; nb++) {
                mma16816(acc[mi][nb], af[mi], &bh[nb >> 1][(nb & 1) * 2]);
                mma16816(acc[mi][nb], af[mi], &bl[nb >> 1][(nb & 1) * 2]);
            }
    }
}

// acc += (A_hi + A_lo) * B:  used by GEMM2 (Y split hi/lo, W single fp16).
__device__ __forceinline__ void mma_block_asplit(float acc[2][8][4],
                                                 uint32_t sAhi, uint32_t sAlo, uint32_t sB,
                                                 int mrow, int ncol, int l) {
    const uint32_t a_lane = (uint32_t)((l & 15) * 128 + (l >> 4) * 16);
    const uint32_t b_lane = (uint32_t)(((l & 7) + ((l >> 4) & 1) * 8) * 128 + ((l >> 3) & 1) * 16);
    #pragma unroll
    for (int kb = 0; kb < 4; kb++) {
        uint32_t ah[2][4], al[2][4], bf[4][4];
        #pragma unroll
        for (int mi = 0; mi < 2; mi++) {
            uint32_t off = (uint32_t)((mrow + mi * 16) * 128 + kb * 32) + a_lane;
            ldsm_x4(ah[mi], sAhi + SWZ128(off));
            ldsm_x4(al[mi], sAlo + SWZ128(off));
        }
        #pragma unroll
        for (int g = 0; g < 4; g++) {
            uint32_t off = (uint32_t)((ncol + g * 16) * 128 + kb * 32) + b_lane;
            ldsm_x4(bf[g], sB + SWZ128(off));
        }
        #pragma unroll
        for (int mi = 0; mi < 2; mi++)
            #pragma unroll
            for (int nb = 0; nb < 8; nb++) {
                mma16816(acc[mi][nb], ah[mi], &bf[nb >> 1][(nb & 1) * 2]);
                mma16816(acc[mi][nb], al[mi], &bf[nb >> 1][(nb & 1) * 2]);
            }
    }
}

// ------------------------------------------------------------------ prepasses
// x [N][128] fp32 -> g_bt_hi/lo[off + j*N + k] fp16
__global__ void prep_bt(const float* __restrict__ X, long off, int N) {
    __shared__ float tile[32][33];
    int k0 = blockIdx.x * 32, j0 = blockIdx.y * 32;
    int tx = threadIdx.x, ty = threadIdx.y;  // (32, 8)
    #pragma unroll
    for (int i = 0; i < 32; i += 8)
        tile[ty + i][tx] = X[(long)(k0 + ty + i) * PD + j0 + tx];
    __syncthreads();
    #pragma unroll
    for (int i = 0; i < 32; i += 8) {
        long j = j0 + ty + i, k = k0 + tx;
        float v = tile[tx][ty + i];
        __half h = __float2half_rn(v);
        g_bt_hi[off + j * N + k] = h;
        g_bt_lo[off + j * N + k] = __float2half_rn(v - __half2float(h));
    }
}
// W fp32 -> fp16, and reset the tile counter (runs every graph replay)
__global__ void prep_aux(const float* __restrict__ W0, const float* __restrict__ W1,
                         const float* __restrict__ W2) {
    int i = blockIdx.x * blockDim.x + threadIdx.x;
    if (i == 0) g_ctr = 0u;
    if (i < PD * PD) {
        g_w16[i]               = __float2half_rn(W0[i]);
        g_w16[PD * PD + i]     = __float2half_rn(W1[i]);
        g_w16[2 * PD * PD + i] = __float2half_rn(W2[i]);
    }
}

// ------------------------------------------------------------------ main
__global__ void __launch_bounds__(256, 1)
scn_main(const float* __restrict__ x0, const float* __restrict__ x1, const float* __restrict__ x2,
         const float* __restrict__ L0, const float* __restrict__ L1, const float* __restrict__ L2,
         const float* __restrict__ bv0, const float* __restrict__ bv1, const float* __restrict__ bv2,
         float* __restrict__ out)
{
    extern __shared__ char smem[];
    const uint32_t sbase = smem_to_u32(smem);
    const int t = threadIdx.x;
    const int l = t & 31, w = t >> 5;
    const int mrow = (w & 3) * 32, ncol = (w >> 2) * 64;
    const int ar = t >> 1, ah2 = t & 1;       // loader row / half (64B per thread per tile)
    volatile int* sidx = (volatile int*)smem;

    for (;;) {
        if (t == 0) *sidx = (int)atomicAdd(&g_ctr, 1u);
        __syncthreads();
        const int idx = *sidx;
        if (idx >= NUM_TILES) break;

        const float *L, *X, *bvec;
        const __half *bth, *btl, *wv;
        float* o;
        long N; int tile;
        if (idx < 128) {                 // branch 1 (heavy) first
            L = L1; X = x1; bvec = bv1; N = PN1; tile = idx;
            bth = g_bt_hi + OFF1; btl = g_bt_lo + OFF1;
            wv = g_w16 + PD * PD; o = out + OFF1;
        } else if (idx < 192) {          // branch 0
            L = L0; X = x0; bvec = bv0; N = PN0; tile = idx - 128;
            bth = g_bt_hi; btl = g_bt_lo; wv = g_w16; o = out;
        } else {                         // branch 2
            L = L2; X = x2; bvec = bv2; N = PN2; tile = idx - 192;
            bth = g_bt_hi + OFF2; btl = g_bt_lo + OFF2;
            wv = g_w16 + 2 * PD * PD; o = out + OFF2;
        }
        const long m0 = (long)tile * 128;
        const int KI = (int)(N >> 6);

        const float* Ap  = L   + (m0 + ar) * N + ah2 * 32;
        const __half* Bh = bth + (long)ar * N + ah2 * 32;
        const __half* Bl = btl + (long)ar * N + ah2 * 32;
        const uint32_t sts_sw[4] = { SWZ128(ar * 128 + ah2 * 64 + 0),
                                     SWZ128(ar * 128 + ah2 * 64 + 16),
                                     SWZ128(ar * 128 + ah2 * 64 + 32),
                                     SWZ128(ar * 128 + ah2 * 64 + 48) };

        float acc[2][8][4];
        #pragma unroll
        for (int mi = 0; mi < 2; mi++)
            #pragma unroll
            for (int nb = 0; nb < 8; nb++)
                #pragma unroll
                for (int i = 0; i < 4; i++) acc[mi][nb][i] = 0.f;

        float4 av[8];
        // ---- prologue: stage 0
        #pragma unroll
        for (int i = 0; i < 8; i++) av[i] = __ldcs((const float4*)Ap + i);
        #pragma unroll
        for (int i = 0; i < 4; i++) {
            CP_ASYNC16(sbase + SMEM_BASE + 16384 + sts_sw[i], Bh + i * 8);
            CP_ASYNC16(sbase + SMEM_BASE + 32768 + sts_sw[i], Bl + i * 8);
        }
        CP_COMMIT();
        #pragma unroll
        for (int i = 0; i < 4; i++) {
            float4 v0 = av[2 * i], v1 = av[2 * i + 1];
            uint4 H = { cvt2(v0.x, v0.y), cvt2(v0.z, v0.w),
                        cvt2(v1.x, v1.y), cvt2(v1.z, v1.w) };
            *(uint4*)(smem + SMEM_BASE + sts_sw[i]) = H;
        }
        CP_WAIT0();
        __syncthreads();

        for (int k = 0; k < KI; k++) {
            const int s = k & 1;
            const bool pf = (k + 1 < KI);
            if (pf) {
                const float* ap = Ap + (long)(k + 1) * 64;
                #pragma unroll
                for (int i = 0; i < 8; i++) av[i] = __ldcs((const float4*)ap + i);
                const uint32_t dst = sbase + SMEM_BASE + (s ^ 1) * STAGE_BYTES;
                #pragma unroll
                for (int i = 0; i < 4; i++) {
                    CP_ASYNC16(dst + 16384 + sts_sw[i], Bh + (long)(k + 1) * 64 + i * 8);
                    CP_ASYNC16(dst + 32768 + sts_sw[i], Bl + (long)(k + 1) * 64 + i * 8);
                }
                CP_COMMIT();
            }
            const uint32_t sA = sbase + SMEM_BASE + s * STAGE_BYTES;
            mma_block_bsplit(acc, sA, sA + 16384, sA + 32768, mrow, ncol, l);
            if (pf) {
                char* dA = smem + SMEM_BASE + (s ^ 1) * STAGE_BYTES;
                #pragma unroll
                for (int i = 0; i < 4; i++) {
                    float4 v0 = av[2 * i], v1 = av[2 * i + 1];
                    uint4 H = { cvt2(v0.x, v0.y), cvt2(v0.z, v0.w),
                                cvt2(v1.x, v1.y), cvt2(v1.z, v1.w) };
                    *(uint4*)(dA + sts_sw[i]) = H;
                }
            }
            CP_WAIT0();
            __syncthreads();
        }

        // ---- epilogue: Y = acc + x -> fp16 hi/lo panels; W -> fp16 panel ----
        char* yh = smem + SMEM_BASE;            // 2 panels x 16K  (k 0-63 | 64-127)
        char* yl = smem + SMEM_BASE + 32768;
        char* wp = smem + SMEM_BASE + 65536;
        #pragma unroll
        for (int mi = 0; mi < 2; mi++)
            #pragma unroll
            for (int nb = 0; nb < 8; nb++) {
                int row = mrow + mi * 16 + (l >> 2);
                int col = ncol + nb * 8 + (l & 3) * 2;
                float2 xv0 = __ldg((const float2*)(X + (m0 + row) * PD + col));
                float2 xv1 = __ldg((const float2*)(X + (m0 + row + 8) * PD + col));
                float y0 = acc[mi][nb][0] + xv0.x, y1 = acc[mi][nb][1] + xv0.y;
                float y2 = acc[mi][nb][2] + xv1.x, y3 = acc[mi][nb][3] + xv1.y;
                __half q0 = __float2half_rn(y0), q1 = __float2half_rn(y1);
                __half q2 = __float2half_rn(y2), q3 = __float2half_rn(y3);
                int p = (col >> 6) * 16384, cb = (col & 63) * 2;
                uint32_t sw0 = SWZ128(row * 128 + cb), sw1 = SWZ128((row + 8) * 128 + cb);
                *(uint32_t*)(yh + p + sw0) = pack_h2(q0, q1);
                *(uint32_t*)(yh + p + sw1) = pack_h2(q2, q3);
                *(uint32_t*)(yl + p + sw0) = pack_h2(__float2half_rn(y0 - __half2float(q0)),
                                                     __float2half_rn(y1 - __half2float(q1)));
                *(uint32_t*)(yl + p + sw1) = pack_h2(__float2half_rn(y2 - __half2float(q2)),
                                                     __float2half_rn(y3 - __half2float(q3)));
            }
        {   // stage W: row n=t>>1, panel=t&1 (64 halfs = 128B)
            const __half* wsrc = wv + (t >> 1) * PD + (t & 1) * 64;
            char* wdst = wp + (t & 1) * 16384;
            #pragma unroll
            for (int i = 0; i < 8; i++)
                *(uint4*)(wdst + SWZ128((t >> 1) * 128 + i * 16)) = *(const uint4*)(wsrc + i * 8);
        }
        __syncthreads();

        // ---- GEMM2: Z = relu(Y @ W^T + b) via HMMA, 2 k-panels x 2 passes ----
        #pragma unroll
        for (int mi = 0; mi < 2; mi++)
            #pragma unroll
            for (int nb = 0; nb < 8; nb++)
                #pragma unroll
                for (int i = 0; i < 4; i++) acc[mi][nb][i] = 0.f;
        mma_block_asplit(acc, sbase + SMEM_BASE,         sbase + SMEM_BASE + 32768,
                              sbase + SMEM_BASE + 65536, mrow, ncol, l);
        mma_block_asplit(acc, sbase + SMEM_BASE + 16384, sbase + SMEM_BASE + 49152,
                              sbase + SMEM_BASE + 81920, mrow, ncol, l);

        #pragma unroll
        for (int mi = 0; mi < 2; mi++)
            #pragma unroll
            for (int nb = 0; nb < 8; nb++) {
                int row = mrow + mi * 16 + (l >> 2);
                int col = ncol + nb * 8 + (l & 3) * 2;
                float2 bb = __ldg((const float2*)(bvec + col));
                float2 z0, z1;
                z0.x = fmaxf(acc[mi][nb][0] + bb.x, 0.f);
                z0.y = fmaxf(acc[mi][nb][1] + bb.y, 0.f);
                z1.x = fmaxf(acc[mi][nb][2] + bb.x, 0.f);
                z1.y = fmaxf(acc[mi][nb][3] + bb.y, 0.f);
                *(float2*)(o + (m0 + row) * PD + col) = z0;
                *(float2*)(o + (m0 + row + 8) * PD + col) = z1;
            }
        __syncthreads();   // protect smem + sidx before next tile
    }
}

// ------------------------------------------------------------------ launch
extern "C" void kernel_launch(void* const* d_in, const int* in_sizes, int n_in,
                              void* d_out, int out_size) {
    const float* x0 = (const float*)d_in[0];
    const float* x1 = (const float*)d_in[1];
    const float* x2 = (const float*)d_in[2];
    const float* L0 = (const float*)d_in[3];
    const float* L1 = (const float*)d_in[4];
    const float* L2 = (const float*)d_in[5];
    const float* W0 = (const float*)d_in[6];
    const float* b0 = (const float*)d_in[7];
    const float* W1 = (const float*)d_in[8];
    const float* b1 = (const float*)d_in[9];
    const float* W2 = (const float*)d_in[10];
    const float* b2 = (const float*)d_in[11];
    float* out = (float*)d_out;

    cudaFuncSetAttribute(scn_main, cudaFuncAttributeMaxDynamicSharedMemorySize, DYN_SMEM);

    dim3 tb(32, 8);
    prep_bt<<<dim3(PN0 / 32, PD / 32), tb>>>(x0, 0L, PN0);
    prep_bt<<<dim3(PN1 / 32, PD / 32), tb>>>(x1, OFF1, PN1);
    prep_bt<<<dim3(PN2 / 32, PD / 32), tb>>>(x2, OFF2, PN2);
    prep_aux<<<64, 256>>>(W0, W1, W2);

    scn_main<<<GRID, 256, DYN_SMEM>>>(x0, x1, x2, L0, L1, L2, b0, b1, b2, out);
}

// round 7
// speedup vs baseline: 1.3029x; 1.3029x over previous
#include <cuda_runtime.h>
#include <cuda_fp16.h>
#include <stdint.h>

#define PN0 8192
#define PN1 16384
#define PN2 8192
#define PD  128
#define NTOT (PN0 + PN1 + PN2)
#define OFF1 ((long)PN0 * PD)
#define OFF2 ((long)(PN0 + PN1) * PD)

#define NUM_TILES 256   // 128 heavy (branch1) + 64 (branch0) + 64 (branch2)
#define GRID 152
#define SMEM_BASE 1024
#define STAGE_BYTES 32768          // A 16K | B 16K
#define DYN_SMEM (SMEM_BASE + 2 * STAGE_BYTES)

// x^T in fp16: g_bt[off + j*N + k] = fp16(x[k][j])
__device__ __half g_bt[(long)NTOT * PD];
__device__ __half g_w16[3 * PD * PD];
__device__ unsigned g_ctr;

#define SWZ128(o) ((uint32_t)(o) ^ ((((uint32_t)(o)) >> 3) & 0x70))

__device__ __forceinline__ uint32_t smem_to_u32(const void* p) {
    uint32_t a;
    asm("{ .reg .u64 t; cvta.to.shared.u64 t, %1; cvt.u32.u64 %0, t; }" : "=r"(a) : "l"(p));
    return a;
}
__device__ __forceinline__ void ldsm_x4(uint32_t* r, uint32_t addr) {
    asm volatile("ldmatrix.sync.aligned.m8n8.x4.shared.b16 {%0,%1,%2,%3}, [%4];"
                 : "=r"(r[0]), "=r"(r[1]), "=r"(r[2]), "=r"(r[3]) : "r"(addr));
}
__device__ __forceinline__ void mma16816(float* c, const uint32_t* a, const uint32_t* b) {
    asm volatile("mma.sync.aligned.m16n8k16.row.col.f32.f16.f16.f32 "
                 "{%0,%1,%2,%3}, {%4,%5,%6,%7}, {%8,%9}, {%0,%1,%2,%3};"
                 : "+f"(c[0]), "+f"(c[1]), "+f"(c[2]), "+f"(c[3])
                 : "r"(a[0]), "r"(a[1]), "r"(a[2]), "r"(a[3]), "r"(b[0]), "r"(b[1]));
}
__device__ __forceinline__ uint32_t cvt2(float x, float y) {
    __half2 t = __float22half2_rn(make_float2(x, y));   // single F2FP.PACK
    return *reinterpret_cast<uint32_t*>(&t);
}
#define CP_ASYNC16(dst, src) \
    asm volatile("cp.async.cg.shared.global [%0], [%1], 16;" :: "r"(dst), "l"(src))
#define CP_COMMIT() asm volatile("cp.async.commit_group;" ::: "memory")
#define CP_WAIT0()  asm volatile("cp.async.wait_group 0;" ::: "memory")

// acc += A * B, single pass.  sA: [128 m][64 k], sB: [128 n][64 k] fp16, SW128.
__device__ __forceinline__ void mma_block1(float acc[2][8][4],
                                           uint32_t sA, uint32_t sB,
                                           int mrow, int ncol, int l) {
    const uint32_t a_lane = (uint32_t)((l & 15) * 128 + (l >> 4) * 16);
    const uint32_t b_lane = (uint32_t)(((l & 7) + ((l >> 4) & 1) * 8) * 128 + ((l >> 3) & 1) * 16);
    #pragma unroll
    for (int kb = 0; kb < 4; kb++) {
        uint32_t af[2][4], bf[4][4];
        #pragma unroll
        for (int mi = 0; mi < 2; mi++) {
            uint32_t off = (uint32_t)((mrow + mi * 16) * 128 + kb * 32) + a_lane;
            ldsm_x4(af[mi], sA + SWZ128(off));
        }
        #pragma unroll
        for (int g = 0; g < 4; g++) {
            uint32_t off = (uint32_t)((ncol + g * 16) * 128 + kb * 32) + b_lane;
            ldsm_x4(bf[g], sB + SWZ128(off));
        }
        #pragma unroll
        for (int mi = 0; mi < 2; mi++)
            #pragma unroll
            for (int nb = 0; nb < 8; nb++)
                mma16816(acc[mi][nb], af[mi], &bf[nb >> 1][(nb & 1) * 2]);
    }
}

// ------------------------------------------------------------------ prepasses
// x [N][128] fp32 -> g_bt[off + j*N + k] fp16
__global__ void prep_bt(const float* __restrict__ X, long off, int N) {
    __shared__ float tile[32][33];
    int k0 = blockIdx.x * 32, j0 = blockIdx.y * 32;
    int tx = threadIdx.x, ty = threadIdx.y;  // (32, 8)
    #pragma unroll
    for (int i = 0; i < 32; i += 8)
        tile[ty + i][tx] = X[(long)(k0 + ty + i) * PD + j0 + tx];
    __syncthreads();
    #pragma unroll
    for (int i = 0; i < 32; i += 8) {
        long j = j0 + ty + i, k = k0 + tx;
        g_bt[off + j * N + k] = __float2half_rn(tile[tx][ty + i]);
    }
}
// W fp32 -> fp16, and reset the tile counter (runs every graph replay)
__global__ void prep_aux(const float* __restrict__ W0, const float* __restrict__ W1,
                         const float* __restrict__ W2) {
    int i = blockIdx.x * blockDim.x + threadIdx.x;
    if (i == 0) g_ctr = 0u;
    if (i < PD * PD) {
        g_w16[i]               = __float2half_rn(W0[i]);
        g_w16[PD * PD + i]     = __float2half_rn(W1[i]);
        g_w16[2 * PD * PD + i] = __float2half_rn(W2[i]);
    }
}

// ------------------------------------------------------------------ main
__global__ void __launch_bounds__(256, 1)
scn_main(const float* __restrict__ x0, const float* __restrict__ x1, const float* __restrict__ x2,
         const float* __restrict__ L0, const float* __restrict__ L1, const float* __restrict__ L2,
         const float* __restrict__ bv0, const float* __restrict__ bv1, const float* __restrict__ bv2,
         float* __restrict__ out)
{
    extern __shared__ char smem[];
    const uint32_t sbase = smem_to_u32(smem);
    const int t = threadIdx.x;
    const int l = t & 31, w = t >> 5;
    const int mrow = (w & 3) * 32, ncol = (w >> 2) * 64;
    const int ar = t >> 1, ah2 = t & 1;       // loader row / half (64B per thread)
    volatile int* sidx = (volatile int*)smem;

    for (;;) {
        if (t == 0) *sidx = (int)atomicAdd(&g_ctr, 1u);
        __syncthreads();
        const int idx = *sidx;
        if (idx >= NUM_TILES) break;

        const float *L, *X, *bvec;
        const __half *bt, *wv;
        float* o;
        long N; int tile;
        if (idx < 128) {                 // branch 1 (heavy) first
            L = L1; X = x1; bvec = bv1; N = PN1; tile = idx;
            bt = g_bt + OFF1; wv = g_w16 + PD * PD; o = out + OFF1;
        } else if (idx < 192) {          // branch 0
            L = L0; X = x0; bvec = bv0; N = PN0; tile = idx - 128;
            bt = g_bt; wv = g_w16; o = out;
        } else {                         // branch 2
            L = L2; X = x2; bvec = bv2; N = PN2; tile = idx - 192;
            bt = g_bt + OFF2; wv = g_w16 + 2 * PD * PD; o = out + OFF2;
        }
        const long m0 = (long)tile * 128;
        const int KI = (int)(N >> 6);

        const float* Ap  = L  + (m0 + ar) * N + ah2 * 32;
        const __half* Bp = bt + (long)ar * N + ah2 * 32;
        const uint32_t sts_sw[4] = { SWZ128(ar * 128 + ah2 * 64 + 0),
                                     SWZ128(ar * 128 + ah2 * 64 + 16),
                                     SWZ128(ar * 128 + ah2 * 64 + 32),
                                     SWZ128(ar * 128 + ah2 * 64 + 48) };

        float acc[2][8][4];
        #pragma unroll
        for (int mi = 0; mi < 2; mi++)
            #pragma unroll
            for (int nb = 0; nb < 8; nb++)
                #pragma unroll
                for (int i = 0; i < 4; i++) acc[mi][nb][i] = 0.f;

        float4 av[8];
        // ---- prologue: stage 0
        #pragma unroll
        for (int i = 0; i < 8; i++) av[i] = __ldcs((const float4*)Ap + i);
        #pragma unroll
        for (int i = 0; i < 4; i++)
            CP_ASYNC16(sbase + SMEM_BASE + 16384 + sts_sw[i], Bp + i * 8);
        CP_COMMIT();
        #pragma unroll
        for (int i = 0; i < 4; i++) {
            float4 v0 = av[2 * i], v1 = av[2 * i + 1];
            uint4 H = { cvt2(v0.x, v0.y), cvt2(v0.z, v0.w),
                        cvt2(v1.x, v1.y), cvt2(v1.z, v1.w) };
            *(uint4*)(smem + SMEM_BASE + sts_sw[i]) = H;
        }
        CP_WAIT0();
        __syncthreads();

        for (int k = 0; k < KI; k++) {
            const int s = k & 1;
            const bool pf = (k + 1 < KI);
            if (pf) {
                const float* ap = Ap + (long)(k + 1) * 64;
                #pragma unroll
                for (int i = 0; i < 8; i++) av[i] = __ldcs((const float4*)ap + i);
                const uint32_t dst = sbase + SMEM_BASE + (s ^ 1) * STAGE_BYTES;
                #pragma unroll
                for (int i = 0; i < 4; i++)
                    CP_ASYNC16(dst + 16384 + sts_sw[i], Bp + (long)(k + 1) * 64 + i * 8);
                CP_COMMIT();
            }
            const uint32_t sA = sbase + SMEM_BASE + s * STAGE_BYTES;
            mma_block1(acc, sA, sA + 16384, mrow, ncol, l);
            if (pf) {
                char* dA = smem + SMEM_BASE + (s ^ 1) * STAGE_BYTES;
                #pragma unroll
                for (int i = 0; i < 4; i++) {
                    float4 v0 = av[2 * i], v1 = av[2 * i + 1];
                    uint4 H = { cvt2(v0.x, v0.y), cvt2(v0.z, v0.w),
                                cvt2(v1.x, v1.y), cvt2(v1.z, v1.w) };
                    *(uint4*)(dA + sts_sw[i]) = H;
                }
            }
            CP_WAIT0();
            __syncthreads();
        }

        // ---- epilogue: Y = acc + x -> fp16 panels; W -> fp16 panels ----
        char* yh = smem + SMEM_BASE;            // 2 panels x 16K  (k 0-63 | 64-127)
        char* wp = smem + SMEM_BASE + 32768;    // 2 panels x 16K
        #pragma unroll
        for (int mi = 0; mi < 2; mi++)
            #pragma unroll
            for (int nb = 0; nb < 8; nb++) {
                int row = mrow + mi * 16 + (l >> 2);
                int col = ncol + nb * 8 + (l & 3) * 2;
                float2 xv0 = __ldg((const float2*)(X + (m0 + row) * PD + col));
                float2 xv1 = __ldg((const float2*)(X + (m0 + row + 8) * PD + col));
                float y0 = acc[mi][nb][0] + xv0.x, y1 = acc[mi][nb][1] + xv0.y;
                float y2 = acc[mi][nb][2] + xv1.x, y3 = acc[mi][nb][3] + xv1.y;
                int p = (col >> 6) * 16384, cb = (col & 63) * 2;
                uint32_t sw0 = SWZ128(row * 128 + cb), sw1 = SWZ128((row + 8) * 128 + cb);
                *(uint32_t*)(yh + p + sw0) = cvt2(y0, y1);
                *(uint32_t*)(yh + p + sw1) = cvt2(y2, y3);
            }
        {   // stage W: row n=t>>1, panel=t&1 (64 halfs = 128B)
            const __half* wsrc = wv + (t >> 1) * PD + (t & 1) * 64;
            char* wdst = wp + (t & 1) * 16384;
            #pragma unroll
            for (int i = 0; i < 8; i++)
                *(uint4*)(wdst + SWZ128((t >> 1) * 128 + i * 16)) = *(const uint4*)(wsrc + i * 8);
        }
        __syncthreads();

        // ---- GEMM2: Z = relu(Y @ W^T + b), single pass, 2 k-panels ----
        #pragma unroll
        for (int mi = 0; mi < 2; mi++)
            #pragma unroll
            for (int nb = 0; nb < 8; nb++)
                #pragma unroll
                for (int i = 0; i < 4; i++) acc[mi][nb][i] = 0.f;
        mma_block1(acc, sbase + SMEM_BASE,         sbase + SMEM_BASE + 32768, mrow, ncol, l);
        mma_block1(acc, sbase + SMEM_BASE + 16384, sbase + SMEM_BASE + 49152, mrow, ncol, l);

        #pragma unroll
        for (int mi = 0; mi < 2; mi++)
            #pragma unroll
            for (int nb = 0; nb < 8; nb++) {
                int row = mrow + mi * 16 + (l >> 2);
                int col = ncol + nb * 8 + (l & 3) * 2;
                float2 bb = __ldg((const float2*)(bvec + col));
                float2 z0, z1;
                z0.x = fmaxf(acc[mi][nb][0] + bb.x, 0.f);
                z0.y = fmaxf(acc[mi][nb][1] + bb.y, 0.f);
                z1.x = fmaxf(acc[mi][nb][2] + bb.x, 0.f);
                z1.y = fmaxf(acc[mi][nb][3] + bb.y, 0.f);
                *(float2*)(o + (m0 + row) * PD + col) = z0;
                *(float2*)(o + (m0 + row + 8) * PD + col) = z1;
            }
        __syncthreads();   // protect smem + sidx before next tile
    }
}

// ------------------------------------------------------------------ launch
extern "C" void kernel_launch(void* const* d_in, const int* in_sizes, int n_in,
                              void* d_out, int out_size) {
    const float* x0 = (const float*)d_in[0];
    const float* x1 = (const float*)d_in[1];
    const float* x2 = (const float*)d_in[2];
    const float* L0 = (const float*)d_in[3];
    const float* L1 = (const float*)d_in[4];
    const float* L2 = (const float*)d_in[5];
    const float* W0 = (const float*)d_in[6];
    const float* b0 = (const float*)d_in[7];
    const float* W1 = (const float*)d_in[8];
    const float* b1 = (const float*)d_in[9];
    const float* W2 = (const float*)d_in[10];
    const float* b2 = (const float*)d_in[11];
    float* out = (float*)d_out;

    cudaFuncSetAttribute(scn_main, cudaFuncAttributeMaxDynamicSharedMemorySize, DYN_SMEM);

    dim3 tb(32, 8);
    prep_bt<<<dim3(PN0 / 32, PD / 32), tb>>>(x0, 0L, PN0);
    prep_bt<<<dim3(PN1 / 32, PD / 32), tb>>>(x1, OFF1, PN1);
    prep_bt<<<dim3(PN2 / 32, PD / 32), tb>>>(x2, OFF2, PN2);
    prep_aux<<<64, 256>>>(W0, W1, W2);

    scn_main<<<GRID, 256, DYN_SMEM>>>(x0, x1, x2, L0, L1, L2, b0, b1, b2, out);
}

// round 8
// speedup vs baseline: 1.5474x; 1.1876x over previous
#include <cuda_runtime.h>
#include <cuda_fp16.h>
#include <stdint.h>

#define PN0 8192
#define PN1 16384
#define PN2 8192
#define PD  128
#define NTOT (PN0 + PN1 + PN2)
#define OFF1 ((long)PN0 * PD)
#define OFF2 ((long)(PN0 + PN1) * PD)

#define NUM_TILES 256   // 128 heavy (branch1) + 64 (branch0) + 64 (branch2)
#define GRID 152
#define THREADS 384               // 8 consumer (MMA) warps + 4 producer warps
#define STAGES 3
#define SMEM_BASE 1024
#define STAGE_BYTES 32768         // A 16K | B 16K
#define DYN_SMEM (SMEM_BASE + STAGES * STAGE_BYTES)

// x^T in fp16: g_bt[off + j*N + k] = fp16(x[k][j])
__device__ __half g_bt[(long)NTOT * PD];
__device__ __half g_w16[3 * PD * PD];
__device__ unsigned g_ctr;

#define SWZ128(o) ((uint32_t)(o) ^ ((((uint32_t)(o)) >> 3) & 0x70))

__device__ __forceinline__ uint32_t smem_to_u32(const void* p) {
    uint32_t a;
    asm("{ .reg .u64 t; cvta.to.shared.u64 t, %1; cvt.u32.u64 %0, t; }" : "=r"(a) : "l"(p));
    return a;
}
__device__ __forceinline__ void ldsm_x4(uint32_t* r, uint32_t addr) {
    asm volatile("ldmatrix.sync.aligned.m8n8.x4.shared.b16 {%0,%1,%2,%3}, [%4];"
                 : "=r"(r[0]), "=r"(r[1]), "=r"(r[2]), "=r"(r[3]) : "r"(addr));
}
__device__ __forceinline__ void mma16816(float* c, const uint32_t* a, const uint32_t* b) {
    asm volatile("mma.sync.aligned.m16n8k16.row.col.f32.f16.f16.f32 "
                 "{%0,%1,%2,%3}, {%4,%5,%6,%7}, {%8,%9}, {%0,%1,%2,%3};"
                 : "+f"(c[0]), "+f"(c[1]), "+f"(c[2]), "+f"(c[3])
                 : "r"(a[0]), "r"(a[1]), "r"(a[2]), "r"(a[3]), "r"(b[0]), "r"(b[1]));
}
__device__ __forceinline__ uint32_t cvt2(float x, float y) {
    __half2 t = __float22half2_rn(make_float2(x, y));
    return *reinterpret_cast<uint32_t*>(&t);
}
#define CP_ASYNC16(dst, src) \
    asm volatile("cp.async.cg.shared.global [%0], [%1], 16;" :: "r"(dst), "l"(src))
#define CP_COMMIT() asm volatile("cp.async.commit_group;" ::: "memory")
#define CP_WAIT0()  asm volatile("cp.async.wait_group 0;" ::: "memory")

#define MBARRIER_INIT(mb, c) \
    asm volatile("mbarrier.init.shared.b64 [%0], %1;" :: "r"((uint32_t)(mb)), "r"((uint32_t)(c)) : "memory")
#define MBARRIER_ARRIVE(mb) \
    asm volatile("mbarrier.arrive.release.cta.shared::cta.b64 _, [%0];" :: "r"((uint32_t)(mb)) : "memory")
#define MBARRIER_WAIT_PARITY(mb, par) do { \
    asm volatile("{\n\t.reg .pred P1;\n\t" \
        "WAIT_LOOP_%=:\n\t" \
        "mbarrier.try_wait.parity.acquire.cta.shared::cta.b64 P1, [%0], %1, 0x989680;\n\t" \
        "@P1 bra.uni WAIT_DONE_%=;\n\t" \
        "bra.uni WAIT_LOOP_%=;\n\t" \
        "WAIT_DONE_%=:\n\t}" :: "r"((uint32_t)(mb)), "r"((uint32_t)(par)) : "memory"); \
} while (0)

// acc += A * B, single pass.  sA: [128 m][64 k], sB: [128 n][64 k] fp16, SW128.
__device__ __forceinline__ void mma_block1(float acc[2][8][4],
                                           uint32_t sA, uint32_t sB,
                                           int mrow, int ncol, int l) {
    const uint32_t a_lane = (uint32_t)((l & 15) * 128 + (l >> 4) * 16);
    const uint32_t b_lane = (uint32_t)(((l & 7) + ((l >> 4) & 1) * 8) * 128 + ((l >> 3) & 1) * 16);
    #pragma unroll
    for (int kb = 0; kb < 4; kb++) {
        uint32_t af[2][4], bf[4][4];
        #pragma unroll
        for (int mi = 0; mi < 2; mi++) {
            uint32_t off = (uint32_t)((mrow + mi * 16) * 128 + kb * 32) + a_lane;
            ldsm_x4(af[mi], sA + SWZ128(off));
        }
        #pragma unroll
        for (int g = 0; g < 4; g++) {
            uint32_t off = (uint32_t)((ncol + g * 16) * 128 + kb * 32) + b_lane;
            ldsm_x4(bf[g], sB + SWZ128(off));
        }
        #pragma unroll
        for (int mi = 0; mi < 2; mi++)
            #pragma unroll
            for (int nb = 0; nb < 8; nb++)
                mma16816(acc[mi][nb], af[mi], &bf[nb >> 1][(nb & 1) * 2]);
    }
}

// ------------------------------------------------------------------ prepasses
__global__ void prep_bt(const float* __restrict__ X, long off, int N) {
    __shared__ float tile[32][33];
    int k0 = blockIdx.x * 32, j0 = blockIdx.y * 32;
    int tx = threadIdx.x, ty = threadIdx.y;  // (32, 8)
    #pragma unroll
    for (int i = 0; i < 32; i += 8)
        tile[ty + i][tx] = X[(long)(k0 + ty + i) * PD + j0 + tx];
    __syncthreads();
    #pragma unroll
    for (int i = 0; i < 32; i += 8) {
        long j = j0 + ty + i, k = k0 + tx;
        g_bt[off + j * N + k] = __float2half_rn(tile[tx][ty + i]);
    }
}
__global__ void prep_aux(const float* __restrict__ W0, const float* __restrict__ W1,
                         const float* __restrict__ W2) {
    int i = blockIdx.x * blockDim.x + threadIdx.x;
    if (i == 0) g_ctr = 0u;
    if (i < PD * PD) {
        g_w16[i]               = __float2half_rn(W0[i]);
        g_w16[PD * PD + i]     = __float2half_rn(W1[i]);
        g_w16[2 * PD * PD + i] = __float2half_rn(W2[i]);
    }
}

// ------------------------------------------------------------------ main
// smem: [0,4) sidx | [8,+8*3) full mbar | [32,+8*3) empty mbar | [1024, +3*32K) stages
__global__ void __launch_bounds__(THREADS, 1)
scn_main(const float* __restrict__ x0, const float* __restrict__ x1, const float* __restrict__ x2,
         const float* __restrict__ L0, const float* __restrict__ L1, const float* __restrict__ L2,
         const float* __restrict__ bv0, const float* __restrict__ bv1, const float* __restrict__ bv2,
         float* __restrict__ out)
{
    extern __shared__ char smem[];
    const uint32_t sbase = smem_to_u32(smem);
    const int t = threadIdx.x;
    const int l = t & 31, w = t >> 5;
    const bool is_mma = (t < 256);
    const int mrow = (w & 3) * 32, ncol = ((w >> 2) & 1) * 64;   // consumers only
    const int pt = t - 256;                                       // producer row 0..127
    volatile int* sidx = (volatile int*)smem;
    const uint32_t mb_full  = sbase + 8;     // 3 x 8B
    const uint32_t mb_empty = sbase + 32;    // 3 x 8B

    for (;;) {
        if (t == 0) {
            *sidx = (int)atomicAdd(&g_ctr, 1u);
            #pragma unroll
            for (int s = 0; s < STAGES; s++) {
                MBARRIER_INIT(mb_full + 8 * s, 4);    // 4 producer warps
                MBARRIER_INIT(mb_empty + 8 * s, 8);   // 8 consumer warps
            }
        }
        __syncthreads();
        const int idx = *sidx;
        if (idx >= NUM_TILES) break;

        const float *L, *X, *bvec;
        const __half *bt, *wv;
        float* o;
        long N; int tile;
        if (idx < 128) {                 // branch 1 (heavy) first
            L = L1; X = x1; bvec = bv1; N = PN1; tile = idx;
            bt = g_bt + OFF1; wv = g_w16 + PD * PD; o = out + OFF1;
        } else if (idx < 192) {          // branch 0
            L = L0; X = x0; bvec = bv0; N = PN0; tile = idx - 128;
            bt = g_bt; wv = g_w16; o = out;
        } else {                         // branch 2
            L = L2; X = x2; bvec = bv2; N = PN2; tile = idx - 192;
            bt = g_bt + OFF2; wv = g_w16 + 2 * PD * PD; o = out + OFF2;
        }
        const long m0 = (long)tile * 128;
        const int KI = (int)(N >> 6);

        float acc[2][8][4];

        if (is_mma) {
            // ---------------- consumers: ldsm + HMMA only ----------------
            #pragma unroll
            for (int mi = 0; mi < 2; mi++)
                #pragma unroll
                for (int nb = 0; nb < 8; nb++)
                    #pragma unroll
                    for (int i = 0; i < 4; i++) acc[mi][nb][i] = 0.f;
            int pf[STAGES] = {0, 0, 0};
            int s = 0;
            for (int k = 0; k < KI; k++) {
                MBARRIER_WAIT_PARITY(mb_full + 8 * s, pf[s]);
                pf[s] ^= 1;
                const uint32_t sA = sbase + SMEM_BASE + s * STAGE_BYTES;
                mma_block1(acc, sA, sA + 16384, mrow, ncol, l);
                __syncwarp();
                if (l == 0) MBARRIER_ARRIVE(mb_empty + 8 * s);
                if (++s == STAGES) s = 0;
            }
        } else {
            // ---------------- producers: LDG A + cvt + STS, cp.async B ----------------
            const float* Ap  = L  + (m0 + pt) * N;
            const __half* Bp = bt + (long)pt * N;
            uint32_t asw[8];
            #pragma unroll
            for (int i = 0; i < 8; i++) asw[i] = SWZ128(pt * 128 + i * 16);
            int pe[STAGES] = {0, 0, 0};
            int s = 0;
            for (int k = 0; k < KI; k++) {
                if (k >= STAGES) {
                    MBARRIER_WAIT_PARITY(mb_empty + 8 * s, pe[s]);
                    pe[s] ^= 1;
                }
                const uint32_t stg = sbase + SMEM_BASE + s * STAGE_BYTES;
                // B: 8 x 16B cp.async (one full 128B row)
                const __half* bsrc = Bp + (long)k * 64;
                #pragma unroll
                for (int i = 0; i < 8; i++)
                    CP_ASYNC16(stg + 16384 + asw[i], bsrc + i * 8);
                CP_COMMIT();
                // A: 16 x float4 LDG -> cvt -> 8 x uint4 STS (one full row)
                const float* asrc = Ap + (long)k * 64;
                float4 av[16];
                #pragma unroll
                for (int i = 0; i < 16; i++) av[i] = __ldcs((const float4*)asrc + i);
                #pragma unroll
                for (int i = 0; i < 8; i++) {
                    float4 v0 = av[2 * i], v1 = av[2 * i + 1];
                    uint4 H = { cvt2(v0.x, v0.y), cvt2(v0.z, v0.w),
                                cvt2(v1.x, v1.y), cvt2(v1.z, v1.w) };
                    *(uint4*)((char*)smem + SMEM_BASE + s * STAGE_BYTES + asw[i]) = H;
                }
                CP_WAIT0();
                __syncwarp();
                if (l == 0) MBARRIER_ARRIVE(mb_full + 8 * s);
                if (++s == STAGES) s = 0;
            }
        }
        __syncthreads();

        // ---- epilogue: Y = acc + x -> fp16 panels; W -> fp16 panels ----
        char* yh = smem + SMEM_BASE;            // 2 panels x 16K  (k 0-63 | 64-127)
        char* wp = smem + SMEM_BASE + 32768;    // 2 panels x 16K
        if (is_mma) {
            #pragma unroll
            for (int mi = 0; mi < 2; mi++)
                #pragma unroll
                for (int nb = 0; nb < 8; nb++) {
                    int row = mrow + mi * 16 + (l >> 2);
                    int col = ncol + nb * 8 + (l & 3) * 2;
                    float2 xv0 = __ldg((const float2*)(X + (m0 + row) * PD + col));
                    float2 xv1 = __ldg((const float2*)(X + (m0 + row + 8) * PD + col));
                    float y0 = acc[mi][nb][0] + xv0.x, y1 = acc[mi][nb][1] + xv0.y;
                    float y2 = acc[mi][nb][2] + xv1.x, y3 = acc[mi][nb][3] + xv1.y;
                    int p = (col >> 6) * 16384, cb = (col & 63) * 2;
                    uint32_t sw0 = SWZ128(row * 128 + cb), sw1 = SWZ128((row + 8) * 128 + cb);
                    *(uint32_t*)(yh + p + sw0) = cvt2(y0, y1);
                    *(uint32_t*)(yh + p + sw1) = cvt2(y2, y3);
                }
            // stage W: row n=t>>1, panel=t&1 (64 halfs = 128B)
            const __half* wsrc = wv + (t >> 1) * PD + (t & 1) * 64;
            char* wdst = wp + (t & 1) * 16384;
            #pragma unroll
            for (int i = 0; i < 8; i++)
                *(uint4*)(wdst + SWZ128((t >> 1) * 128 + i * 16)) = *(const uint4*)(wsrc + i * 8);
        }
        __syncthreads();

        // ---- GEMM2: Z = relu(Y @ W^T + b), single pass, 2 k-panels ----
        if (is_mma) {
            #pragma unroll
            for (int mi = 0; mi < 2; mi++)
                #pragma unroll
                for (int nb = 0; nb < 8; nb++)
                    #pragma unroll
                    for (int i = 0; i < 4; i++) acc[mi][nb][i] = 0.f;
            mma_block1(acc, sbase + SMEM_BASE,         sbase + SMEM_BASE + 32768, mrow, ncol, l);
            mma_block1(acc, sbase + SMEM_BASE + 16384, sbase + SMEM_BASE + 49152, mrow, ncol, l);

            #pragma unroll
            for (int mi = 0; mi < 2; mi++)
                #pragma unroll
                for (int nb = 0; nb < 8; nb++) {
                    int row = mrow + mi * 16 + (l >> 2);
                    int col = ncol + nb * 8 + (l & 3) * 2;
                    float2 bb = __ldg((const float2*)(bvec + col));
                    float2 z0, z1;
                    z0.x = fmaxf(acc[mi][nb][0] + bb.x, 0.f);
                    z0.y = fmaxf(acc[mi][nb][1] + bb.y, 0.f);
                    z1.x = fmaxf(acc[mi][nb][2] + bb.x, 0.f);
                    z1.y = fmaxf(acc[mi][nb][3] + bb.y, 0.f);
                    *(float2*)(o + (m0 + row) * PD + col) = z0;
                    *(float2*)(o + (m0 + row + 8) * PD + col) = z1;
                }
        }
        __syncthreads();   // protect smem + barriers before next tile
    }
}

// ------------------------------------------------------------------ launch
extern "C" void kernel_launch(void* const* d_in, const int* in_sizes, int n_in,
                              void* d_out, int out_size) {
    const float* x0 = (const float*)d_in[0];
    const float* x1 = (const float*)d_in[1];
    const float* x2 = (const float*)d_in[2];
    const float* L0 = (const float*)d_in[3];
    const float* L1 = (const float*)d_in[4];
    const float* L2 = (const float*)d_in[5];
    const float* W0 = (const float*)d_in[6];
    const float* b0 = (const float*)d_in[7];
    const float* W1 = (const float*)d_in[8];
    const float* b1 = (const float*)d_in[9];
    const float* W2 = (const float*)d_in[10];
    const float* b2 = (const float*)d_in[11];
    float* out = (float*)d_out;

    cudaFuncSetAttribute(scn_main, cudaFuncAttributeMaxDynamicSharedMemorySize, DYN_SMEM);

    dim3 tb(32, 8);
    prep_bt<<<dim3(PN0 / 32, PD / 32), tb>>>(x0, 0L, PN0);
    prep_bt<<<dim3(PN1 / 32, PD / 32), tb>>>(x1, OFF1, PN1);
    prep_bt<<<dim3(PN2 / 32, PD / 32), tb>>>(x2, OFF2, PN2);
    prep_aux<<<64, 256>>>(W0, W1, W2);

    scn_main<<<GRID, THREADS, DYN_SMEM>>>(x0, x1, x2, L0, L1, L2, b0, b1, b2, out);
}